// round 5
// baseline (speedup 1.0000x reference)
#include <cuda_runtime.h>
#include <math.h>

#define BB 2
#define NN 2048
#define CC 64
#define NK 9
#define KC 576            // NK * CC
#define GG 5              // 5x5 bins, cell 0.2 > prune radius 0.171
#define NCELL 25

#define R2f     0.01f
#define DILf    0.05f
#define FULLM   0xffffffffu

// knorm = 315 / (64 * pi * R^9), R = 0.1
#define KNORMf ((float)(315.0 / (64.0 * 3.14159265358979323846 * 1e-9)))

// ---------------- scratch ---------------------------------------------------
__device__ float  g_coef[BB * NN];
__device__ float  g_Wp[(CC / 2) * KC * 2];  // [o/2][kc][2]
__device__ float  g_dcoefS[BB * NN * CC];   // SORTED rows: [b][slot][c]
__device__ float2 g_sPos[BB * NN + 32];     // sorted positions + sentinel pad
__device__ int    g_slotOf[BB * NN];        // orig j -> slot
__device__ int    g_origOf[BB * NN];        // slot -> orig j
__device__ int    g_cellCnt[BB * NCELL];
__device__ int    g_cellStart[BB * NCELL];

__device__ __forceinline__ int cell_of(float x, float y) {
    int cx = (int)(x * (float)GG); cx = min(GG - 1, max(0, cx));
    int cy = (int)(y * (float)GG); cy = min(GG - 1, max(0, cy));
    return cy * GG + cx;
}

// ---------------- packed f32x2 helpers --------------------------------------
__device__ __forceinline__ unsigned long long pk2(float lo, float hi) {
    unsigned long long r;
    asm("mov.b64 %0, {%1, %2};" : "=l"(r) : "f"(lo), "f"(hi));
    return r;
}
__device__ __forceinline__ void fma2(unsigned long long& d,
                                     unsigned long long a,
                                     unsigned long long b) {
    asm("fma.rn.f32x2 %0, %1, %2, %0;" : "+l"(d) : "l"(a), "l"(b));
}

// ---------------- prep1: coef + weight repack + sentinel --------------------
__global__ void prep1_kernel(const float* __restrict__ locs,
                             const float* __restrict__ density,
                             const float* __restrict__ weight) {
    int idx = blockIdx.x * blockDim.x + threadIdx.x;
    if (idx < BB * NN) {
        float im  = locs[idx * 3 + 2];
        float den = density[idx];
        g_coef[idx] = 1.0f / (im * den);
    }
    if (idx < 32) g_sPos[BB * NN + idx] = make_float2(1e9f, 1e9f);
    if (idx < CC * CC * NK) {
        int o = idx / (CC * NK);
        int r = idx - o * (CC * NK);
        int c = r / NK;
        int k = r - c * NK;
        int kc = k * CC + c;
        g_Wp[((o >> 1) * KC + kc) * 2 + (o & 1)] = weight[idx];
    }
}

// ---------------- binning: count + scan + ordered scatter, 1 block/batch ----
__global__ __launch_bounds__(800) void bin_kernel(const float* __restrict__ locs) {
    __shared__ int s_cnt[NCELL];
    int b    = blockIdx.x;
    int tid  = threadIdx.x;
    int w    = tid >> 5;       // warp = cell
    int lane = tid & 31;

    if (w < NCELL) {
        int cnt = 0;
        for (int j0 = 0; j0 < NN; j0 += 32) {
            const float* lp = locs + (size_t)(b * NN + j0 + lane) * 3;
            int c = cell_of(lp[0], lp[1]);
            cnt += __popc(__ballot_sync(FULLM, c == w));
        }
        if (lane == 0) s_cnt[w] = cnt;
    }
    __syncthreads();
    if (w < NCELL) {
        int v = (lane < w) ? s_cnt[lane] : 0;
        #pragma unroll
        for (int o = 16; o; o >>= 1) v += __shfl_xor_sync(FULLM, v, o);
        int off = v;                              // exclusive prefix
        if (lane == 0) {
            g_cellStart[b * NCELL + w] = off;
            g_cellCnt[b * NCELL + w]   = s_cnt[w];
        }
        for (int j0 = 0; j0 < NN; j0 += 32) {
            int j = j0 + lane;
            const float* lp = locs + (size_t)(b * NN + j) * 3;
            float x = lp[0], y = lp[1];
            bool match = (cell_of(x, y) == w);
            unsigned m = __ballot_sync(FULLM, match);
            int rank = __popc(m & ((1u << lane) - 1u));
            if (match) {
                int slot = off + rank;
                g_slotOf[b * NN + j]    = slot;
                g_origOf[b * NN + slot] = j;
                g_sPos[b * NN + slot]   = make_float2(x, y);
            }
            off += __popc(m);
        }
    }
}

// ---------------- prep2: transpose data -> SORTED dcoefS --------------------
__global__ void prep2_kernel(const float* __restrict__ data) {
    __shared__ float s[32][33];
    int jt = blockIdx.x;      // 0..63
    int ct = blockIdx.y;      // 0..1
    int b  = blockIdx.z;      // 0..1
    int tx = threadIdx.x, ty = threadIdx.y;

    int c = ct * 32 + ty;
    int j = jt * 32 + tx;
    s[ty][tx] = data[(b * CC + c) * NN + j];
    __syncthreads();

    int j2 = jt * 32 + ty;
    int c2 = ct * 32 + tx;
    int slot = g_slotOf[b * NN + j2];
    g_dcoefS[((size_t)(b * NN + slot)) * CC + c2] =
        s[tx][ty] * g_coef[b * NN + j2];
}

// ---------------- main: 2 warps/particle, gather + fused GEMV ---------------
__device__ __forceinline__ float wfun(float t) {
    t = fmaxf(t, 0.0f);
    return (t * t) * (t * KNORMf);
}

#define ENT 10   // ulonglongs per entry: 9 dup'd w-pairs + slot

__global__ __launch_bounds__(256) void convsp_main_kernel(
        const float* __restrict__ bias, float* __restrict__ out) {
    __shared__ unsigned long long buf[8][32 * ENT];   // 20.5 KB
    __shared__ float2 part[4][32];                    // pair partial results

    int b    = blockIdx.x >> 9;           // 1024 blocks: 512 per batch
    int tid  = threadIdx.x;
    int warp = tid >> 5;
    int lane = tid & 31;
    int p    = warp >> 1;                 // particle index in block: 0..3
    int half = warp & 1;                  // which warp of the pair

    int i_slot = (blockIdx.x & 511) * 4 + p;          // SORTED order
    const float2* sp = g_sPos + (size_t)b * NN;

    float2 pi = __ldg(&sp[i_slot]);
    float xi = pi.x, yi = pi.y;

    int cx = min(GG - 1, max(0, (int)(xi * (float)GG)));
    int cy = min(GG - 1, max(0, (int)(yi * (float)GG)));
    int cx0 = max(0, cx - 1), cx1 = min(GG - 1, cx + 1);
    int cy0 = max(0, cy - 1), cy1 = min(GG - 1, cy + 1);

    unsigned long long a0 = 0, a1 = 0, a2 = 0, a3 = 0, a4 = 0,
                       a5 = 0, a6 = 0, a7 = 0, a8 = 0;

    const unsigned long long* dcU =
        reinterpret_cast<const unsigned long long*>(g_dcoefS)
        + ((size_t)b * NN * 32) + lane;

    unsigned long long* wb = buf[warp];

    for (int yy = cy0; yy <= cy1; yy++) {
        int c0 = b * NCELL + yy * GG + cx0;
        int c1 = b * NCELL + yy * GG + cx1;
        int rs = __ldg(&g_cellStart[c0]);
        int re = __ldg(&g_cellStart[c1]) + __ldg(&g_cellCnt[c1]);

        // pair-split: this warp takes alternating 32-wide tiles
        for (int t = rs + half * 32; t < re; t += 64) {
            // ---- Phase A: lane-parallel w-compute + compaction ----
            int slot = t + lane;
            float2 pj = __ldg(&sp[slot]);     // sentinel pad covers tail
            float dx = xi - pj.x;
            float dy = yi - pj.y;
            if (slot >= re) dx = 1e9f;

            float bxm = dx - DILf, bxp = dx + DILf;
            float bym = dy - DILf, byp = dy + DILf;
            float rx0 = fmaf(-bxm, bxm, R2f);
            float rx1 = fmaf(-dx,  dx,  R2f);
            float rx2 = fmaf(-bxp, bxp, R2f);
            float ay0 = bym * bym;
            float ay1 = dy * dy;
            float ay2 = byp * byp;

            float w0 = wfun(rx0 - ay0);
            float w1 = wfun(rx0 - ay1);
            float w2 = wfun(rx0 - ay2);
            float w3 = wfun(rx1 - ay0);
            float w4 = wfun(rx1 - ay1);
            float w5 = wfun(rx1 - ay2);
            float w6 = wfun(rx2 - ay0);
            float w7 = wfun(rx2 - ay1);
            float w8 = wfun(rx2 - ay2);

            float ssum = ((w0 + w1) + (w2 + w3)) + ((w4 + w5) + (w6 + w7)) + w8;
            bool active = ssum > 0.0f;

            unsigned m = __ballot_sync(FULLM, active);
            int cnt = __popc(m);
            if (active) {
                int rank = __popc(m & ((1u << lane) - 1u));
                ulonglong2* e2 = reinterpret_cast<ulonglong2*>(wb + rank * ENT);
                e2[0] = make_ulonglong2(pk2(w0, w0), pk2(w1, w1));
                e2[1] = make_ulonglong2(pk2(w2, w2), pk2(w3, w3));
                e2[2] = make_ulonglong2(pk2(w4, w4), pk2(w5, w5));
                e2[3] = make_ulonglong2(pk2(w6, w6), pk2(w7, w7));
                e2[4] = make_ulonglong2(pk2(w8, w8),
                                        (unsigned long long)(unsigned)slot);
            }
            __syncwarp();

            // ---- Phase B: entry-serial, lanes over channels, FFMA2 ----
#define BODY(E)                                                               \
            {                                                                 \
                const ulonglong2* q =                                         \
                    reinterpret_cast<const ulonglong2*>(wb + (E) * ENT);      \
                ulonglong2 q0 = q[0], q1 = q[1], q2 = q[2],                   \
                           q3 = q[3], q4 = q[4];                              \
                int sl = (int)(unsigned)q4.y;                                 \
                unsigned long long dc = __ldg(&dcU[(size_t)sl << 5]);         \
                fma2(a0, q0.x, dc); fma2(a1, q0.y, dc);                       \
                fma2(a2, q1.x, dc); fma2(a3, q1.y, dc);                       \
                fma2(a4, q2.x, dc); fma2(a5, q2.y, dc);                       \
                fma2(a6, q3.x, dc); fma2(a7, q3.y, dc);                       \
                fma2(a8, q4.x, dc);                                           \
            }
            int e = 0;
            for (; e + 2 <= cnt; e += 2) { BODY(e) BODY(e + 1) }
            if (e < cnt) { BODY(e) }
#undef BODY
            __syncwarp();
        }
    }

    // ---- deposit partial field (576 floats) into this warp's smem buf ----
    wb[0 * 32 + lane] = a0;  wb[1 * 32 + lane] = a1;  wb[2 * 32 + lane] = a2;
    wb[3 * 32 + lane] = a3;  wb[4 * 32 + lane] = a4;  wb[5 * 32 + lane] = a5;
    wb[6 * 32 + lane] = a6;  wb[7 * 32 + lane] = a7;  wb[8 * 32 + lane] = a8;

    // pair barrier: both warps' deposits visible
    asm volatile("bar.sync %0, 64;" :: "r"(p + 1) : "memory");

    // ---- fused GEMV over this warp's kc half; lane = o-pair --------------
    const float4* fqA = reinterpret_cast<const float4*>(buf[2 * p]);
    const float4* fqB = reinterpret_cast<const float4*>(buf[2 * p + 1]);
    const float4* wp  = reinterpret_cast<const float4*>(
        g_Wp + (size_t)lane * KC * 2);
    float p00 = 0.f, p01 = 0.f, p10 = 0.f, p11 = 0.f;
    float p20 = 0.f, p21 = 0.f, p30 = 0.f, p31 = 0.f;

    int q0i = half * (KC / 8);           // 72 float4-iters per warp
    #pragma unroll 4
    for (int q = q0i; q < q0i + KC / 8; q++) {
        float4 fa = fqA[q];
        float4 fb = fqB[q];
        float4 w01 = __ldg(&wp[q * 2 + 0]);   // kc = 4q, 4q+1
        float4 w23 = __ldg(&wp[q * 2 + 1]);   // kc = 4q+2, 4q+3
        float fx = fa.x + fb.x, fy = fa.y + fb.y;
        float fz = fa.z + fb.z, fw = fa.w + fb.w;
        p00 = fmaf(w01.x, fx, p00); p01 = fmaf(w01.y, fx, p01);
        p10 = fmaf(w01.z, fy, p10); p11 = fmaf(w01.w, fy, p11);
        p20 = fmaf(w23.x, fz, p20); p21 = fmaf(w23.y, fz, p21);
        p30 = fmaf(w23.z, fw, p30); p31 = fmaf(w23.w, fw, p31);
    }
    float r0 = (p00 + p10) + (p20 + p30);
    float r1 = (p01 + p11) + (p21 + p31);

    if (half == 1) part[p][lane] = make_float2(r0, r1);
    asm volatile("bar.sync %0, 64;" :: "r"(p + 1) : "memory");

    if (half == 0) {
        float2 pr = part[p][lane];
        int orig = __ldg(&g_origOf[b * NN + i_slot]);
        float2 bv = *reinterpret_cast<const float2*>(&bias[2 * lane]);
        out[((size_t)b * CC + 2 * lane)     * NN + orig] = bv.x + r0 + pr.x;
        out[((size_t)b * CC + 2 * lane + 1) * NN + orig] = bv.y + r1 + pr.y;
    }
}

// ---------------- launcher --------------------------------------------------
extern "C" void kernel_launch(void* const* d_in, const int* in_sizes, int n_in,
                              void* d_out, int out_size) {
    // Bind inputs by unique element counts:
    // locs 12288, data 262144, density 4096, weight 36864, bias 64.
    const float* locs = nullptr;
    const float* data = nullptr;
    const float* density = nullptr;
    const float* weight = nullptr;
    const float* bias = nullptr;
    for (int idx = 0; idx < n_in; idx++) {
        switch (in_sizes[idx]) {
            case 12288:  locs    = (const float*)d_in[idx]; break;
            case 262144: data    = (const float*)d_in[idx]; break;
            case 4096:   density = (const float*)d_in[idx]; break;
            case 36864:  weight  = (const float*)d_in[idx]; break;
            case 64:     bias    = (const float*)d_in[idx]; break;
            default: break;
        }
    }
    float* out = (float*)d_out;

    prep1_kernel<<<144, 256>>>(locs, density, weight);
    bin_kernel<<<BB, 800>>>(locs);
    prep2_kernel<<<dim3(64, 2, 2), dim3(32, 32)>>>(data);
    convsp_main_kernel<<<1024, 256>>>(bias, out);
}

// round 6
// speedup vs baseline: 2.2432x; 2.2432x over previous
#include <cuda_runtime.h>
#include <math.h>

#define BB 2
#define NN 2048
#define CC 64
#define NK 9
#define KC 576            // NK * CC
#define GG 5              // 5x5 bins, cell 0.2 > prune radius 0.171
#define NCELL 25

#define R2f     0.01f
#define DILf    0.05f
#define FULLM   0xffffffffu

// knorm = 315 / (64 * pi * R^9), R = 0.1
#define KNORMf ((float)(315.0 / (64.0 * 3.14159265358979323846 * 1e-9)))

// ---------------- scratch ---------------------------------------------------
__device__ float  g_coef[BB * NN];
__device__ float  g_Wt[KC * CC];            // [kc][o]  (kc = k*64+c)
__device__ float  g_dcoefS[BB * NN * CC];   // SORTED rows: [b][slot][c]
__device__ float2 g_sPos[BB * NN + 32];     // sorted positions + sentinel pad
__device__ int    g_slotOf[BB * NN];        // orig j -> slot
__device__ int    g_origOf[BB * NN];        // slot -> orig j
__device__ int    g_cellCnt[BB * NCELL];
__device__ int    g_cellStart[BB * NCELL];

__device__ __forceinline__ int cell_of(float x, float y) {
    int cx = (int)(x * (float)GG); cx = min(GG - 1, max(0, cx));
    int cy = (int)(y * (float)GG); cy = min(GG - 1, max(0, cy));
    return cy * GG + cx;
}

// ---------------- packed f32x2 helpers --------------------------------------
__device__ __forceinline__ unsigned long long pk2(float lo, float hi) {
    unsigned long long r;
    asm("mov.b64 %0, {%1, %2};" : "=l"(r) : "f"(lo), "f"(hi));
    return r;
}
__device__ __forceinline__ void fma2(unsigned long long& d,
                                     unsigned long long a,
                                     unsigned long long b) {
    asm("fma.rn.f32x2 %0, %1, %2, %0;" : "+l"(d) : "l"(a), "l"(b));
}

// ---------------- prep1: coef + weight transpose + sentinel -----------------
__global__ void prep1_kernel(const float* __restrict__ locs,
                             const float* __restrict__ density,
                             const float* __restrict__ weight) {
    int idx = blockIdx.x * blockDim.x + threadIdx.x;
    if (idx < BB * NN) {
        float im  = locs[idx * 3 + 2];
        float den = density[idx];
        g_coef[idx] = 1.0f / (im * den);
    }
    if (idx < 32) g_sPos[BB * NN + idx] = make_float2(1e9f, 1e9f);
    if (idx < CC * CC * NK) {
        int o = idx / (CC * NK);
        int r = idx - o * (CC * NK);
        int c = r / NK;
        int k = r - c * NK;
        g_Wt[(k * CC + c) * CC + o] = weight[idx];
    }
}

// ---------------- binning: count + scan + ordered scatter, 1 block/batch ----
__global__ __launch_bounds__(800) void bin_kernel(const float* __restrict__ locs) {
    __shared__ int s_cnt[NCELL];
    int b    = blockIdx.x;
    int tid  = threadIdx.x;
    int w    = tid >> 5;       // warp = cell
    int lane = tid & 31;

    if (w < NCELL) {
        int cnt = 0;
        for (int j0 = 0; j0 < NN; j0 += 32) {
            const float* lp = locs + (size_t)(b * NN + j0 + lane) * 3;
            int c = cell_of(lp[0], lp[1]);
            cnt += __popc(__ballot_sync(FULLM, c == w));
        }
        if (lane == 0) s_cnt[w] = cnt;
    }
    __syncthreads();
    if (w < NCELL) {
        int v = (lane < w) ? s_cnt[lane] : 0;
        #pragma unroll
        for (int o = 16; o; o >>= 1) v += __shfl_xor_sync(FULLM, v, o);
        int off = v;                              // exclusive prefix
        if (lane == 0) {
            g_cellStart[b * NCELL + w] = off;
            g_cellCnt[b * NCELL + w]   = s_cnt[w];
        }
        for (int j0 = 0; j0 < NN; j0 += 32) {
            int j = j0 + lane;
            const float* lp = locs + (size_t)(b * NN + j) * 3;
            float x = lp[0], y = lp[1];
            bool match = (cell_of(x, y) == w);
            unsigned m = __ballot_sync(FULLM, match);
            int rank = __popc(m & ((1u << lane) - 1u));
            if (match) {
                int slot = off + rank;
                g_slotOf[b * NN + j]    = slot;
                g_origOf[b * NN + slot] = j;
                g_sPos[b * NN + slot]   = make_float2(x, y);
            }
            off += __popc(m);
        }
    }
}

// ---------------- prep2: transpose data -> SORTED dcoefS --------------------
__global__ void prep2_kernel(const float* __restrict__ data) {
    __shared__ float s[32][33];
    int jt = blockIdx.x;      // 0..63
    int ct = blockIdx.y;      // 0..1
    int b  = blockIdx.z;      // 0..1
    int tx = threadIdx.x, ty = threadIdx.y;

    int c = ct * 32 + ty;
    int j = jt * 32 + tx;
    s[ty][tx] = data[(b * CC + c) * NN + j];
    __syncthreads();

    int j2 = jt * 32 + ty;
    int c2 = ct * 32 + tx;
    int slot = g_slotOf[b * NN + j2];
    g_dcoefS[((size_t)(b * NN + slot)) * CC + c2] =
        s[tx][ty] * g_coef[b * NN + j2];
}

// ---------------- main: 2 warps/particle, gather + fused GEMV ---------------
__device__ __forceinline__ float wfun(float t) {
    t = fmaxf(t, 0.0f);
    return (t * t) * (t * KNORMf);
}

#define ENT 10   // ulonglongs per entry: 9 dup'd w-pairs + slot

__global__ __launch_bounds__(128, 9) void convsp_main_kernel(
        const float* __restrict__ bias, float* __restrict__ out) {
    __shared__ unsigned long long buf[4][32 * ENT];   // 10.25 KB
    __shared__ float2 part[2][32];                    // pair partial results

    int b    = blockIdx.x >> 10;          // 2048 blocks: 1024 per batch
    int tid  = threadIdx.x;
    int warp = tid >> 5;                  // 0..3
    int lane = tid & 31;
    int p    = warp >> 1;                 // particle in block: 0..1
    int half = warp & 1;                  // which warp of the pair

    int i_slot = (blockIdx.x & 1023) * 2 + p;         // SORTED order
    const float2* sp = g_sPos + (size_t)b * NN;

    float2 pi = __ldg(&sp[i_slot]);
    float xi = pi.x, yi = pi.y;

    int cx = min(GG - 1, max(0, (int)(xi * (float)GG)));
    int cy = min(GG - 1, max(0, (int)(yi * (float)GG)));
    int cx0 = max(0, cx - 1), cx1 = min(GG - 1, cx + 1);
    int cy0 = max(0, cy - 1), cy1 = min(GG - 1, cy + 1);

    unsigned long long a0 = 0, a1 = 0, a2 = 0, a3 = 0, a4 = 0,
                       a5 = 0, a6 = 0, a7 = 0, a8 = 0;

    const unsigned long long* dcU =
        reinterpret_cast<const unsigned long long*>(g_dcoefS)
        + ((size_t)b * NN * 32) + lane;

    unsigned long long* wb = buf[warp];

    for (int yy = cy0; yy <= cy1; yy++) {
        int c0 = b * NCELL + yy * GG + cx0;
        int c1 = b * NCELL + yy * GG + cx1;
        int rs = __ldg(&g_cellStart[c0]);
        int re = __ldg(&g_cellStart[c1]) + __ldg(&g_cellCnt[c1]);

        // pair-split: this warp takes alternating 32-wide tiles
        for (int t = rs + half * 32; t < re; t += 64) {
            // ---- Phase A: lane-parallel w-compute + compaction ----
            int slot = t + lane;
            float2 pj = __ldg(&sp[slot]);     // sentinel pad covers tail
            float dx = xi - pj.x;
            float dy = yi - pj.y;
            if (slot >= re) dx = 1e9f;

            float bxm = dx - DILf, bxp = dx + DILf;
            float bym = dy - DILf, byp = dy + DILf;
            float rx0 = fmaf(-bxm, bxm, R2f);
            float rx1 = fmaf(-dx,  dx,  R2f);
            float rx2 = fmaf(-bxp, bxp, R2f);
            float ay0 = bym * bym;
            float ay1 = dy * dy;
            float ay2 = byp * byp;

            float w0 = wfun(rx0 - ay0);
            float w1 = wfun(rx0 - ay1);
            float w2 = wfun(rx0 - ay2);
            float w3 = wfun(rx1 - ay0);
            float w4 = wfun(rx1 - ay1);
            float w5 = wfun(rx1 - ay2);
            float w6 = wfun(rx2 - ay0);
            float w7 = wfun(rx2 - ay1);
            float w8 = wfun(rx2 - ay2);

            float ssum = ((w0 + w1) + (w2 + w3)) + ((w4 + w5) + (w6 + w7)) + w8;
            bool active = ssum > 0.0f;

            unsigned m = __ballot_sync(FULLM, active);
            int cnt = __popc(m);
            if (active) {
                int rank = __popc(m & ((1u << lane) - 1u));
                ulonglong2* e2 = reinterpret_cast<ulonglong2*>(wb + rank * ENT);
                e2[0] = make_ulonglong2(pk2(w0, w0), pk2(w1, w1));
                e2[1] = make_ulonglong2(pk2(w2, w2), pk2(w3, w3));
                e2[2] = make_ulonglong2(pk2(w4, w4), pk2(w5, w5));
                e2[3] = make_ulonglong2(pk2(w6, w6), pk2(w7, w7));
                e2[4] = make_ulonglong2(pk2(w8, w8),
                                        (unsigned long long)(unsigned)slot);
            }
            __syncwarp();

            // ---- Phase B: entry-serial, lanes over channels, FFMA2 ----
#define BODY(E)                                                               \
            {                                                                 \
                const ulonglong2* q =                                         \
                    reinterpret_cast<const ulonglong2*>(wb + (E) * ENT);      \
                ulonglong2 q0 = q[0], q1 = q[1], q2 = q[2],                   \
                           q3 = q[3], q4 = q[4];                              \
                int sl = (int)(unsigned)q4.y;                                 \
                unsigned long long dc = __ldg(&dcU[(size_t)sl << 5]);         \
                fma2(a0, q0.x, dc); fma2(a1, q0.y, dc);                       \
                fma2(a2, q1.x, dc); fma2(a3, q1.y, dc);                       \
                fma2(a4, q2.x, dc); fma2(a5, q2.y, dc);                       \
                fma2(a6, q3.x, dc); fma2(a7, q3.y, dc);                       \
                fma2(a8, q4.x, dc);                                           \
            }
            int e = 0;
            for (; e + 2 <= cnt; e += 2) { BODY(e) BODY(e + 1) }
            if (e < cnt) { BODY(e) }
#undef BODY
            __syncwarp();
        }
    }

    // ---- deposit partial field (576 floats) into this warp's smem buf ----
    wb[0 * 32 + lane] = a0;  wb[1 * 32 + lane] = a1;  wb[2 * 32 + lane] = a2;
    wb[3 * 32 + lane] = a3;  wb[4 * 32 + lane] = a4;  wb[5 * 32 + lane] = a5;
    wb[6 * 32 + lane] = a6;  wb[7 * 32 + lane] = a7;  wb[8 * 32 + lane] = a8;

    // pair barrier: both warps' deposits visible
    asm volatile("bar.sync %0, 64;" :: "r"(p + 1) : "memory");

    // ---- fused GEMV over this warp's kc half; lane = o-pair --------------
    // Wt[kc][o]: lane loads o-pair (2*lane, 2*lane+1) -> 32 lanes span 256B.
    const float4* fqA = reinterpret_cast<const float4*>(buf[2 * p]);
    const float4* fqB = reinterpret_cast<const float4*>(buf[2 * p + 1]);
    const float2* wt  = reinterpret_cast<const float2*>(g_Wt) + lane;
    float p00 = 0.f, p01 = 0.f, p10 = 0.f, p11 = 0.f;
    float p20 = 0.f, p21 = 0.f, p30 = 0.f, p31 = 0.f;

    int q0i = half * (KC / 8);           // 72 quad-iters per warp
    #pragma unroll 4
    for (int q = q0i; q < q0i + KC / 8; q++) {
        float4 fa = fqA[q];
        float4 fb = fqB[q];
        float2 v0 = __ldg(&wt[(q * 4 + 0) * 32]);
        float2 v1 = __ldg(&wt[(q * 4 + 1) * 32]);
        float2 v2 = __ldg(&wt[(q * 4 + 2) * 32]);
        float2 v3 = __ldg(&wt[(q * 4 + 3) * 32]);
        float fx = fa.x + fb.x, fy = fa.y + fb.y;
        float fz = fa.z + fb.z, fw = fa.w + fb.w;
        p00 = fmaf(v0.x, fx, p00); p01 = fmaf(v0.y, fx, p01);
        p10 = fmaf(v1.x, fy, p10); p11 = fmaf(v1.y, fy, p11);
        p20 = fmaf(v2.x, fz, p20); p21 = fmaf(v2.y, fz, p21);
        p30 = fmaf(v3.x, fw, p30); p31 = fmaf(v3.y, fw, p31);
    }
    float r0 = (p00 + p10) + (p20 + p30);
    float r1 = (p01 + p11) + (p21 + p31);

    if (half == 1) part[p][lane] = make_float2(r0, r1);
    asm volatile("bar.sync %0, 64;" :: "r"(p + 1) : "memory");

    if (half == 0) {
        float2 pr = part[p][lane];
        int orig = __ldg(&g_origOf[b * NN + i_slot]);
        float2 bv = *reinterpret_cast<const float2*>(&bias[2 * lane]);
        out[((size_t)b * CC + 2 * lane)     * NN + orig] = bv.x + r0 + pr.x;
        out[((size_t)b * CC + 2 * lane + 1) * NN + orig] = bv.y + r1 + pr.y;
    }
}

// ---------------- launcher --------------------------------------------------
extern "C" void kernel_launch(void* const* d_in, const int* in_sizes, int n_in,
                              void* d_out, int out_size) {
    // Bind inputs by unique element counts:
    // locs 12288, data 262144, density 4096, weight 36864, bias 64.
    const float* locs = nullptr;
    const float* data = nullptr;
    const float* density = nullptr;
    const float* weight = nullptr;
    const float* bias = nullptr;
    for (int idx = 0; idx < n_in; idx++) {
        switch (in_sizes[idx]) {
            case 12288:  locs    = (const float*)d_in[idx]; break;
            case 262144: data    = (const float*)d_in[idx]; break;
            case 4096:   density = (const float*)d_in[idx]; break;
            case 36864:  weight  = (const float*)d_in[idx]; break;
            case 64:     bias    = (const float*)d_in[idx]; break;
            default: break;
        }
    }
    float* out = (float*)d_out;

    prep1_kernel<<<144, 256>>>(locs, density, weight);
    bin_kernel<<<BB, 800>>>(locs);
    prep2_kernel<<<dim3(64, 2, 2), dim3(32, 32)>>>(data);
    convsp_main_kernel<<<2048, 128>>>(bias, out);
}

// round 7
// speedup vs baseline: 2.2780x; 1.0155x over previous
#include <cuda_runtime.h>
#include <math.h>

#define BB 2
#define NN 2048
#define CC 64
#define NK 9
#define KC 576            // NK * CC
#define GG 5              // 5x5 bins, cell 0.2 > prune radius 0.171
#define NCELL 25

#define R2f     0.01f
#define DILf    0.05f
#define FULLM   0xffffffffu

// knorm = 315 / (64 * pi * R^9), R = 0.1
#define KNORMf ((float)(315.0 / (64.0 * 3.14159265358979323846 * 1e-9)))

// ---------------- scratch ---------------------------------------------------
__device__ float  g_coef[BB * NN];
__device__ float  g_Wt[KC * CC];            // [kc][o]  (kc = k*64+c)
__device__ float  g_dcoefS[BB * NN * CC];   // SORTED rows: [b][slot][c]
__device__ float2 g_sPos[BB * NN + 32];     // sorted positions + sentinel pad
__device__ int    g_slotOf[BB * NN];        // orig j -> slot
__device__ int    g_origOf[BB * NN];        // slot -> orig j
__device__ int    g_cellCnt[BB * NCELL];
__device__ int    g_cellStart[BB * NCELL];

__device__ __forceinline__ int cell_of(float x, float y) {
    int cx = (int)(x * (float)GG); cx = min(GG - 1, max(0, cx));
    int cy = (int)(y * (float)GG); cy = min(GG - 1, max(0, cy));
    return cy * GG + cx;
}

// ---------------- packed f32x2 helpers --------------------------------------
__device__ __forceinline__ unsigned long long pk2(float lo, float hi) {
    unsigned long long r;
    asm("mov.b64 %0, {%1, %2};" : "=l"(r) : "f"(lo), "f"(hi));
    return r;
}
__device__ __forceinline__ void fma2(unsigned long long& d,
                                     unsigned long long a,
                                     unsigned long long b) {
    asm("fma.rn.f32x2 %0, %1, %2, %0;" : "+l"(d) : "l"(a), "l"(b));
}

// ---------------- prep1: coef + weight transpose + sentinel -----------------
__global__ void prep1_kernel(const float* __restrict__ locs,
                             const float* __restrict__ density,
                             const float* __restrict__ weight) {
    int idx = blockIdx.x * blockDim.x + threadIdx.x;
    if (idx < BB * NN) {
        float im  = locs[idx * 3 + 2];
        float den = density[idx];
        g_coef[idx] = 1.0f / (im * den);
    }
    if (idx < 32) g_sPos[BB * NN + idx] = make_float2(1e9f, 1e9f);
    if (idx < CC * CC * NK) {
        int o = idx / (CC * NK);
        int r = idx - o * (CC * NK);
        int c = r / NK;
        int k = r - c * NK;
        g_Wt[(k * CC + c) * CC + o] = weight[idx];
    }
}

// ---------------- binning: count + scan + ordered scatter, 1 block/batch ----
__global__ __launch_bounds__(800) void bin_kernel(const float* __restrict__ locs) {
    __shared__ int s_cnt[NCELL];
    int b    = blockIdx.x;
    int tid  = threadIdx.x;
    int w    = tid >> 5;       // warp = cell
    int lane = tid & 31;

    if (w < NCELL) {
        int cnt = 0;
        for (int j0 = 0; j0 < NN; j0 += 32) {
            const float* lp = locs + (size_t)(b * NN + j0 + lane) * 3;
            int c = cell_of(lp[0], lp[1]);
            cnt += __popc(__ballot_sync(FULLM, c == w));
        }
        if (lane == 0) s_cnt[w] = cnt;
    }
    __syncthreads();
    if (w < NCELL) {
        int v = (lane < w) ? s_cnt[lane] : 0;
        #pragma unroll
        for (int o = 16; o; o >>= 1) v += __shfl_xor_sync(FULLM, v, o);
        int off = v;                              // exclusive prefix
        if (lane == 0) {
            g_cellStart[b * NCELL + w] = off;
            g_cellCnt[b * NCELL + w]   = s_cnt[w];
        }
        for (int j0 = 0; j0 < NN; j0 += 32) {
            int j = j0 + lane;
            const float* lp = locs + (size_t)(b * NN + j) * 3;
            float x = lp[0], y = lp[1];
            bool match = (cell_of(x, y) == w);
            unsigned m = __ballot_sync(FULLM, match);
            int rank = __popc(m & ((1u << lane) - 1u));
            if (match) {
                int slot = off + rank;
                g_slotOf[b * NN + j]    = slot;
                g_origOf[b * NN + slot] = j;
                g_sPos[b * NN + slot]   = make_float2(x, y);
            }
            off += __popc(m);
        }
    }
}

// ---------------- prep2: transpose data -> SORTED dcoefS --------------------
__global__ void prep2_kernel(const float* __restrict__ data) {
    __shared__ float s[32][33];
    int jt = blockIdx.x;      // 0..63
    int ct = blockIdx.y;      // 0..1
    int b  = blockIdx.z;      // 0..1
    int tx = threadIdx.x, ty = threadIdx.y;

    int c = ct * 32 + ty;
    int j = jt * 32 + tx;
    s[ty][tx] = data[(b * CC + c) * NN + j];
    __syncthreads();

    int j2 = jt * 32 + ty;
    int c2 = ct * 32 + tx;
    int slot = g_slotOf[b * NN + j2];
    g_dcoefS[((size_t)(b * NN + slot)) * CC + c2] =
        s[tx][ty] * g_coef[b * NN + j2];
}

// ---------------- main: 2 warps/particle, gather + fused GEMV ---------------
__device__ __forceinline__ float wfun(float t) {
    t = fmaxf(t, 0.0f);
    return (t * t) * (t * KNORMf);
}

#define ENT 10   // ulonglongs per entry: 9 dup'd w-pairs + slot

__global__ __launch_bounds__(128, 9) void convsp_main_kernel(
        const float* __restrict__ bias, float* __restrict__ out) {
    __shared__ unsigned long long buf[4][32 * ENT];   // 10.25 KB
    __shared__ float2 part[2][32];                    // pair partial results

    int b    = blockIdx.x >> 10;          // 2048 blocks: 1024 per batch
    int tid  = threadIdx.x;
    int warp = tid >> 5;                  // 0..3
    int lane = tid & 31;
    int p    = warp >> 1;                 // particle in block: 0..1
    int half = warp & 1;                  // which warp of the pair

    int i_slot = (blockIdx.x & 1023) * 2 + p;         // SORTED order
    const float2* sp = g_sPos + (size_t)b * NN;

    float2 pi = __ldg(&sp[i_slot]);
    float xi = pi.x, yi = pi.y;

    int cx = min(GG - 1, max(0, (int)(xi * (float)GG)));
    int cy = min(GG - 1, max(0, (int)(yi * (float)GG)));
    int cx0 = max(0, cx - 1), cx1 = min(GG - 1, cx + 1);
    int cy0 = max(0, cy - 1), cy1 = min(GG - 1, cy + 1);

    unsigned long long a0 = 0, a1 = 0, a2 = 0, a3 = 0, a4 = 0,
                       a5 = 0, a6 = 0, a7 = 0, a8 = 0;

    const unsigned long long* dcU =
        reinterpret_cast<const unsigned long long*>(g_dcoefS)
        + ((size_t)b * NN * 32) + lane;

    unsigned long long* wb = buf[warp];

    for (int yy = cy0; yy <= cy1; yy++) {
        int c0 = b * NCELL + yy * GG + cx0;
        int c1 = b * NCELL + yy * GG + cx1;
        int rs = __ldg(&g_cellStart[c0]);
        int re = __ldg(&g_cellStart[c1]) + __ldg(&g_cellCnt[c1]);

        // pair-split: this warp takes alternating 32-wide tiles
        for (int t = rs + half * 32; t < re; t += 64) {
            // ---- Phase A: lane-parallel w-compute + compaction ----
            int slot = t + lane;
            float2 pj = __ldg(&sp[slot]);     // sentinel pad covers tail
            float dx = xi - pj.x;
            float dy = yi - pj.y;
            if (slot >= re) dx = 1e9f;

            float bxm = dx - DILf, bxp = dx + DILf;
            float bym = dy - DILf, byp = dy + DILf;
            float rx0 = fmaf(-bxm, bxm, R2f);
            float rx1 = fmaf(-dx,  dx,  R2f);
            float rx2 = fmaf(-bxp, bxp, R2f);
            float ay0 = bym * bym;
            float ay1 = dy * dy;
            float ay2 = byp * byp;

            float w0 = wfun(rx0 - ay0);
            float w1 = wfun(rx0 - ay1);
            float w2 = wfun(rx0 - ay2);
            float w3 = wfun(rx1 - ay0);
            float w4 = wfun(rx1 - ay1);
            float w5 = wfun(rx1 - ay2);
            float w6 = wfun(rx2 - ay0);
            float w7 = wfun(rx2 - ay1);
            float w8 = wfun(rx2 - ay2);

            float ssum = ((w0 + w1) + (w2 + w3)) + ((w4 + w5) + (w6 + w7)) + w8;
            bool active = ssum > 0.0f;

            unsigned m = __ballot_sync(FULLM, active);
            int cnt = __popc(m);
            if (active) {
                int rank = __popc(m & ((1u << lane) - 1u));
                ulonglong2* e2 = reinterpret_cast<ulonglong2*>(wb + rank * ENT);
                e2[0] = make_ulonglong2(pk2(w0, w0), pk2(w1, w1));
                e2[1] = make_ulonglong2(pk2(w2, w2), pk2(w3, w3));
                e2[2] = make_ulonglong2(pk2(w4, w4), pk2(w5, w5));
                e2[3] = make_ulonglong2(pk2(w6, w6), pk2(w7, w7));
                e2[4] = make_ulonglong2(pk2(w8, w8),
                                        (unsigned long long)(unsigned)slot);
            }
            __syncwarp();

            // ---- Phase B: entry-serial, lanes over channels, FFMA2 ----
#define BODY(E)                                                               \
            {                                                                 \
                const ulonglong2* q =                                         \
                    reinterpret_cast<const ulonglong2*>(wb + (E) * ENT);      \
                ulonglong2 q0 = q[0], q1 = q[1], q2 = q[2],                   \
                           q3 = q[3], q4 = q[4];                              \
                int sl = (int)(unsigned)q4.y;                                 \
                unsigned long long dc = __ldg(&dcU[(size_t)sl << 5]);         \
                fma2(a0, q0.x, dc); fma2(a1, q0.y, dc);                       \
                fma2(a2, q1.x, dc); fma2(a3, q1.y, dc);                       \
                fma2(a4, q2.x, dc); fma2(a5, q2.y, dc);                       \
                fma2(a6, q3.x, dc); fma2(a7, q3.y, dc);                       \
                fma2(a8, q4.x, dc);                                           \
            }
            int e = 0;
            for (; e + 2 <= cnt; e += 2) { BODY(e) BODY(e + 1) }
            if (e < cnt) { BODY(e) }
#undef BODY
            __syncwarp();
        }
    }

    // ---- deposit partial field (576 floats) into this warp's smem buf ----
    wb[0 * 32 + lane] = a0;  wb[1 * 32 + lane] = a1;  wb[2 * 32 + lane] = a2;
    wb[3 * 32 + lane] = a3;  wb[4 * 32 + lane] = a4;  wb[5 * 32 + lane] = a5;
    wb[6 * 32 + lane] = a6;  wb[7 * 32 + lane] = a7;  wb[8 * 32 + lane] = a8;

    // block barrier (barrier 0 only -- named barriers cap CTA residency)
    __syncthreads();

    // ---- fused GEMV over this warp's kc half; lane = o-pair --------------
    // Wt[kc][o]: lane loads o-pair (2*lane, 2*lane+1) -> 32 lanes span 256B.
    const float4* fqA = reinterpret_cast<const float4*>(buf[2 * p]);
    const float4* fqB = reinterpret_cast<const float4*>(buf[2 * p + 1]);
    const float2* wt  = reinterpret_cast<const float2*>(g_Wt) + lane;
    float p00 = 0.f, p01 = 0.f, p10 = 0.f, p11 = 0.f;
    float p20 = 0.f, p21 = 0.f, p30 = 0.f, p31 = 0.f;

    int q0i = half * (KC / 8);           // 72 quad-iters per warp
    #pragma unroll 4
    for (int q = q0i; q < q0i + KC / 8; q++) {
        float4 fa = fqA[q];
        float4 fb = fqB[q];
        float2 v0 = __ldg(&wt[(q * 4 + 0) * 32]);
        float2 v1 = __ldg(&wt[(q * 4 + 1) * 32]);
        float2 v2 = __ldg(&wt[(q * 4 + 2) * 32]);
        float2 v3 = __ldg(&wt[(q * 4 + 3) * 32]);
        float fx = fa.x + fb.x, fy = fa.y + fb.y;
        float fz = fa.z + fb.z, fw = fa.w + fb.w;
        p00 = fmaf(v0.x, fx, p00); p01 = fmaf(v0.y, fx, p01);
        p10 = fmaf(v1.x, fy, p10); p11 = fmaf(v1.y, fy, p11);
        p20 = fmaf(v2.x, fz, p20); p21 = fmaf(v2.y, fz, p21);
        p30 = fmaf(v3.x, fw, p30); p31 = fmaf(v3.y, fw, p31);
    }
    float r0 = (p00 + p10) + (p20 + p30);
    float r1 = (p01 + p11) + (p21 + p31);

    if (half == 1) part[p][lane] = make_float2(r0, r1);
    __syncthreads();

    if (half == 0) {
        float2 pr = part[p][lane];
        int orig = __ldg(&g_origOf[b * NN + i_slot]);
        float2 bv = *reinterpret_cast<const float2*>(&bias[2 * lane]);
        out[((size_t)b * CC + 2 * lane)     * NN + orig] = bv.x + r0 + pr.x;
        out[((size_t)b * CC + 2 * lane + 1) * NN + orig] = bv.y + r1 + pr.y;
    }
}

// ---------------- launcher --------------------------------------------------
extern "C" void kernel_launch(void* const* d_in, const int* in_sizes, int n_in,
                              void* d_out, int out_size) {
    // Bind inputs by unique element counts:
    // locs 12288, data 262144, density 4096, weight 36864, bias 64.
    const float* locs = nullptr;
    const float* data = nullptr;
    const float* density = nullptr;
    const float* weight = nullptr;
    const float* bias = nullptr;
    for (int idx = 0; idx < n_in; idx++) {
        switch (in_sizes[idx]) {
            case 12288:  locs    = (const float*)d_in[idx]; break;
            case 262144: data    = (const float*)d_in[idx]; break;
            case 4096:   density = (const float*)d_in[idx]; break;
            case 36864:  weight  = (const float*)d_in[idx]; break;
            case 64:     bias    = (const float*)d_in[idx]; break;
            default: break;
        }
    }
    float* out = (float*)d_out;

    prep1_kernel<<<144, 256>>>(locs, density, weight);
    bin_kernel<<<BB, 800>>>(locs);
    prep2_kernel<<<dim3(64, 2, 2), dim3(32, 32)>>>(data);
    convsp_main_kernel<<<2048, 128>>>(bias, out);
}

// round 10
// speedup vs baseline: 2.8669x; 1.2585x over previous
#include <cuda_runtime.h>
#include <math.h>

#define BB 2
#define NN 2048
#define CC 64
#define NK 9
#define KC 576            // NK * CC
#define GG 5              // 5x5 bins, cell 0.2 > prune radius 0.171
#define NCELL 25

#define R2f     0.01f
#define DILf    0.05f
#define FULLM   0xffffffffu

// knorm = 315 / (64 * pi * R^9), R = 0.1
#define KNORMf ((float)(315.0 / (64.0 * 3.14159265358979323846 * 1e-9)))

// ---------------- scratch ---------------------------------------------------
__device__ float  g_coef[BB * NN];
__device__ float  g_Wt[KC * CC];            // [kc][o]  (kc = k*64+c)
__device__ float  g_dcoefS[BB * NN * CC];   // SORTED rows: [b][slot][c]
__device__ float2 g_sPos[BB * NN + 32];     // sorted positions + sentinel pad
__device__ int    g_slotOf[BB * NN];        // orig j -> slot
__device__ int    g_origOf[BB * NN];        // slot -> orig j
__device__ int    g_cellCnt[BB * NCELL];
__device__ int    g_cellStart[BB * NCELL];

__device__ __forceinline__ int cell_of(float x, float y) {
    int cx = (int)(x * (float)GG); cx = min(GG - 1, max(0, cx));
    int cy = (int)(y * (float)GG); cy = min(GG - 1, max(0, cy));
    return cy * GG + cx;
}

// ---------------- prep1: coef + weight transpose + sentinel -----------------
__global__ void prep1_kernel(const float* __restrict__ locs,
                             const float* __restrict__ density,
                             const float* __restrict__ weight) {
    int idx = blockIdx.x * blockDim.x + threadIdx.x;
    if (idx < BB * NN) {
        float im  = locs[idx * 3 + 2];
        float den = density[idx];
        g_coef[idx] = 1.0f / (im * den);
    }
    if (idx < 32) g_sPos[BB * NN + idx] = make_float2(1e9f, 1e9f);
    if (idx < CC * CC * NK) {
        int o = idx / (CC * NK);
        int r = idx - o * (CC * NK);
        int c = r / NK;
        int k = r - c * NK;
        g_Wt[(k * CC + c) * CC + o] = weight[idx];
    }
}

// ---------------- binning: smem-cached count + scan + ordered scatter -------
__global__ __launch_bounds__(800) void bin_kernel(const float* __restrict__ locs) {
    __shared__ float2 s_pos[NN];
    __shared__ int    s_cell[NN];
    __shared__ int    s_cnt[NCELL];

    int b    = blockIdx.x;
    int tid  = threadIdx.x;
    int w    = tid >> 5;       // warp = cell (warps 0..24)
    int lane = tid & 31;

    // one pass caches positions + cell ids
    for (int t = tid; t < NN; t += 800) {
        const float* lp = locs + (size_t)(b * NN + t) * 3;
        float x = lp[0], y = lp[1];
        s_pos[t]  = make_float2(x, y);
        s_cell[t] = cell_of(x, y);
    }
    __syncthreads();

    if (w < NCELL) {
        int cnt = 0;
        for (int j0 = 0; j0 < NN; j0 += 32)
            cnt += __popc(__ballot_sync(FULLM, s_cell[j0 + lane] == w));
        if (lane == 0) s_cnt[w] = cnt;
    }
    __syncthreads();
    if (w < NCELL) {
        int v = (lane < w) ? s_cnt[lane] : 0;
        #pragma unroll
        for (int o = 16; o; o >>= 1) v += __shfl_xor_sync(FULLM, v, o);
        int off = v;                              // exclusive prefix
        if (lane == 0) {
            g_cellStart[b * NCELL + w] = off;
            g_cellCnt[b * NCELL + w]   = s_cnt[w];
        }
        for (int j0 = 0; j0 < NN; j0 += 32) {
            int j = j0 + lane;
            bool match = (s_cell[j] == w);
            unsigned m = __ballot_sync(FULLM, match);
            int rank = __popc(m & ((1u << lane) - 1u));
            if (match) {
                int slot = off + rank;
                g_slotOf[b * NN + j]    = slot;
                g_origOf[b * NN + slot] = j;
                g_sPos[b * NN + slot]   = s_pos[j];
            }
            off += __popc(m);
        }
    }
}

// ---------------- prep2: transpose data -> SORTED dcoefS --------------------
__global__ __launch_bounds__(256) void prep2_kernel(const float* __restrict__ data) {
    __shared__ float s[32][33];
    int jt = blockIdx.x;      // 0..63
    int ct = blockIdx.y;      // 0..1
    int b  = blockIdx.z;      // 0..1
    int tx = threadIdx.x;     // 0..31
    int ty = threadIdx.y;     // 0..7

    #pragma unroll
    for (int i = 0; i < 4; i++) {
        int c = ct * 32 + ty + 8 * i;
        s[ty + 8 * i][tx] = data[((size_t)(b * CC + c)) * NN + jt * 32 + tx];
    }
    __syncthreads();
    #pragma unroll
    for (int i = 0; i < 4; i++) {
        int j2 = jt * 32 + ty + 8 * i;
        int slot = g_slotOf[b * NN + j2];
        g_dcoefS[((size_t)(b * NN + slot)) * CC + ct * 32 + tx] =
            s[tx][ty + 8 * i] * g_coef[b * NN + j2];
    }
}

// ---------------- main: 2 warps/particle, slim entries + pipelined drain ----
__device__ __forceinline__ float wfun(float t) {
    t = fmaxf(t, 0.0f);
    return (t * t) * (t * KNORMf);
}

#define WBF 640   // floats per warp region (2560B): 33*12=396 entry floats, 576 deposit

__global__ __launch_bounds__(128, 9) void convsp_main_kernel(
        const float* __restrict__ bias, float* __restrict__ out) {
    __shared__ __align__(16) float buf[4][WBF];       // 10.25 KB
    __shared__ __align__(16) float2 part[2][32];      // pair partial results

    int b    = blockIdx.x >> 10;          // 2048 blocks: 1024 per batch
    int tid  = threadIdx.x;
    int warp = tid >> 5;                  // 0..3
    int lane = tid & 31;
    int p    = warp >> 1;                 // particle in block: 0..1
    int half = warp & 1;                  // which warp of the pair

    int i_slot = (blockIdx.x & 1023) * 2 + p;         // SORTED order
    const float2* sp = g_sPos + (size_t)b * NN;

    float2 pi = __ldg(&sp[i_slot]);
    float xi = pi.x, yi = pi.y;

    int cx = min(GG - 1, max(0, (int)(xi * (float)GG)));
    int cy = min(GG - 1, max(0, (int)(yi * (float)GG)));
    int cx0 = max(0, cx - 1), cx1 = min(GG - 1, cx + 1);
    int cy0 = max(0, cy - 1), cy1 = min(GG - 1, cy + 1);

    float a0x = 0.f, a1x = 0.f, a2x = 0.f, a3x = 0.f, a4x = 0.f,
          a5x = 0.f, a6x = 0.f, a7x = 0.f, a8x = 0.f;
    float a0y = 0.f, a1y = 0.f, a2y = 0.f, a3y = 0.f, a4y = 0.f,
          a5y = 0.f, a6y = 0.f, a7y = 0.f, a8y = 0.f;

    const float2* dcF = reinterpret_cast<const float2*>(g_dcoefS)
                        + ((size_t)b * NN * 32) + lane;

    float* wbF = buf[warp];

    for (int yy = cy0; yy <= cy1; yy++) {
        int c0 = b * NCELL + yy * GG + cx0;
        int c1 = b * NCELL + yy * GG + cx1;
        int rs = __ldg(&g_cellStart[c0]);
        int re = __ldg(&g_cellStart[c1]) + __ldg(&g_cellCnt[c1]);

        // pair-split: this warp takes alternating 32-wide tiles
        for (int t = rs + half * 32; t < re; t += 64) {
            // ---- Phase A: lane-parallel w-compute + compaction ----
            int slot = t + lane;
            float2 pj = __ldg(&sp[slot]);     // sentinel pad covers tail
            float dx = xi - pj.x;
            float dy = yi - pj.y;
            if (slot >= re) dx = 1e9f;

            float bxm = dx - DILf, bxp = dx + DILf;
            float bym = dy - DILf, byp = dy + DILf;
            float rx0 = fmaf(-bxm, bxm, R2f);
            float rx1 = fmaf(-dx,  dx,  R2f);
            float rx2 = fmaf(-bxp, bxp, R2f);
            float ay0 = bym * bym;
            float ay1 = dy * dy;
            float ay2 = byp * byp;

            float w0 = wfun(rx0 - ay0);
            float w1 = wfun(rx0 - ay1);
            float w2 = wfun(rx0 - ay2);
            float w3 = wfun(rx1 - ay0);
            float w4 = wfun(rx1 - ay1);
            float w5 = wfun(rx1 - ay2);
            float w6 = wfun(rx2 - ay0);
            float w7 = wfun(rx2 - ay1);
            float w8 = wfun(rx2 - ay2);

            // exact union test: some rx_a - ay_b > 0  <=>  some w > 0
            bool active = fmaxf(rx0, fmaxf(rx1, rx2)) >
                          fminf(ay0, fminf(ay1, ay2));

            unsigned m = __ballot_sync(FULLM, active);
            int cnt = __popc(m);
            if (active) {
                int rank = __popc(m & ((1u << lane) - 1u));
                float* e = wbF + rank * 12;
                *reinterpret_cast<float4*>(e + 0) =
                    make_float4(w0, w1, w2, w3);
                *reinterpret_cast<float4*>(e + 4) =
                    make_float4(w4, w5, w6, w7);
                *reinterpret_cast<float4*>(e + 8) =
                    make_float4(w8, __int_as_float(slot), 0.f, 0.f);
            }
            // sentinel entry at rank cnt (prefetch target, never FMA'd)
            if (lane == 0)
                *reinterpret_cast<float4*>(wbF + cnt * 12 + 8) =
                    make_float4(0.f, __int_as_float(0), 0.f, 0.f);
            __syncwarp();

            // ---- Phase B: entry-serial, software-pipelined dc load ----
            if (cnt > 0) {
                float4 q2 = *reinterpret_cast<const float4*>(wbF + 8);
                float2 dc = __ldg(&dcF[(size_t)__float_as_int(q2.y) << 5]);
                float w8c = q2.x;
                for (int e = 0; e < cnt; e++) {
                    const float* ep = wbF + e * 12;
                    float4 q2n = *reinterpret_cast<const float4*>(ep + 20);
                    float2 dcn = __ldg(
                        &dcF[(size_t)__float_as_int(q2n.y) << 5]);
                    float4 q0 = *reinterpret_cast<const float4*>(ep + 0);
                    float4 q1 = *reinterpret_cast<const float4*>(ep + 4);
                    a0x = fmaf(q0.x, dc.x, a0x); a0y = fmaf(q0.x, dc.y, a0y);
                    a1x = fmaf(q0.y, dc.x, a1x); a1y = fmaf(q0.y, dc.y, a1y);
                    a2x = fmaf(q0.z, dc.x, a2x); a2y = fmaf(q0.z, dc.y, a2y);
                    a3x = fmaf(q0.w, dc.x, a3x); a3y = fmaf(q0.w, dc.y, a3y);
                    a4x = fmaf(q1.x, dc.x, a4x); a4y = fmaf(q1.x, dc.y, a4y);
                    a5x = fmaf(q1.y, dc.x, a5x); a5y = fmaf(q1.y, dc.y, a5y);
                    a6x = fmaf(q1.z, dc.x, a6x); a6y = fmaf(q1.z, dc.y, a6y);
                    a7x = fmaf(q1.w, dc.x, a7x); a7y = fmaf(q1.w, dc.y, a7y);
                    a8x = fmaf(w8c,  dc.x, a8x); a8y = fmaf(w8c,  dc.y, a8y);
                    w8c = q2n.x;
                    dc  = dcn;
                }
            }
            __syncwarp();
        }
    }

    // ---- deposit partial field (576 floats) into this warp's smem buf ----
    __syncwarp();
    {
        float2* wf2 = reinterpret_cast<float2*>(wbF);
        wf2[0 * 32 + lane] = make_float2(a0x, a0y);
        wf2[1 * 32 + lane] = make_float2(a1x, a1y);
        wf2[2 * 32 + lane] = make_float2(a2x, a2y);
        wf2[3 * 32 + lane] = make_float2(a3x, a3y);
        wf2[4 * 32 + lane] = make_float2(a4x, a4y);
        wf2[5 * 32 + lane] = make_float2(a5x, a5y);
        wf2[6 * 32 + lane] = make_float2(a6x, a6y);
        wf2[7 * 32 + lane] = make_float2(a7x, a7y);
        wf2[8 * 32 + lane] = make_float2(a8x, a8y);
    }
    __syncthreads();

    // ---- fused GEMV over this warp's kc half; lane = o-pair --------------
    const float4* fqA = reinterpret_cast<const float4*>(buf[2 * p]);
    const float4* fqB = reinterpret_cast<const float4*>(buf[2 * p + 1]);
    const float2* wt  = reinterpret_cast<const float2*>(g_Wt) + lane;
    float p00 = 0.f, p01 = 0.f, p10 = 0.f, p11 = 0.f;
    float p20 = 0.f, p21 = 0.f, p30 = 0.f, p31 = 0.f;

    int q0i = half * (KC / 8);           // 72 quad-iters per warp
    #pragma unroll 4
    for (int q = q0i; q < q0i + KC / 8; q++) {
        float4 fa = fqA[q];
        float4 fb = fqB[q];
        float2 v0 = __ldg(&wt[(q * 4 + 0) * 32]);
        float2 v1 = __ldg(&wt[(q * 4 + 1) * 32]);
        float2 v2 = __ldg(&wt[(q * 4 + 2) * 32]);
        float2 v3 = __ldg(&wt[(q * 4 + 3) * 32]);
        float fx = fa.x + fb.x, fy = fa.y + fb.y;
        float fz = fa.z + fb.z, fw = fa.w + fb.w;
        p00 = fmaf(v0.x, fx, p00); p01 = fmaf(v0.y, fx, p01);
        p10 = fmaf(v1.x, fy, p10); p11 = fmaf(v1.y, fy, p11);
        p20 = fmaf(v2.x, fz, p20); p21 = fmaf(v2.y, fz, p21);
        p30 = fmaf(v3.x, fw, p30); p31 = fmaf(v3.y, fw, p31);
    }
    float r0 = (p00 + p10) + (p20 + p30);
    float r1 = (p01 + p11) + (p21 + p31);

    if (half == 1) part[p][lane] = make_float2(r0, r1);
    __syncthreads();

    if (half == 0) {
        float2 pr = part[p][lane];
        int orig = __ldg(&g_origOf[b * NN + i_slot]);
        float2 bv = *reinterpret_cast<const float2*>(&bias[2 * lane]);
        out[((size_t)b * CC + 2 * lane)     * NN + orig] = bv.x + r0 + pr.x;
        out[((size_t)b * CC + 2 * lane + 1) * NN + orig] = bv.y + r1 + pr.y;
    }
}

// ---------------- launcher --------------------------------------------------
extern "C" void kernel_launch(void* const* d_in, const int* in_sizes, int n_in,
                              void* d_out, int out_size) {
    // Bind inputs by unique element counts:
    // locs 12288, data 262144, density 4096, weight 36864, bias 64.
    const float* locs = nullptr;
    const float* data = nullptr;
    const float* density = nullptr;
    const float* weight = nullptr;
    const float* bias = nullptr;
    for (int idx = 0; idx < n_in; idx++) {
        switch (in_sizes[idx]) {
            case 12288:  locs    = (const float*)d_in[idx]; break;
            case 262144: data    = (const float*)d_in[idx]; break;
            case 4096:   density = (const float*)d_in[idx]; break;
            case 36864:  weight  = (const float*)d_in[idx]; break;
            case 64:     bias    = (const float*)d_in[idx]; break;
            default: break;
        }
    }
    float* out = (float*)d_out;

    prep1_kernel<<<144, 256>>>(locs, density, weight);
    bin_kernel<<<BB, 800>>>(locs);
    prep2_kernel<<<dim3(64, 2, 2), dim3(32, 8)>>>(data);
    convsp_main_kernel<<<2048, 128>>>(bias, out);
}

// round 11
// speedup vs baseline: 3.1882x; 1.1121x over previous
#include <cuda_runtime.h>
#include <cuda_fp16.h>
#include <math.h>

#define BB 2
#define NN 2048
#define CC 64
#define NK 9
#define KC 576            // NK * CC
#define GG 5              // 5x5 bins, cell 0.2 > prune radius 0.171
#define NCELL 25

#define R2f     0.01f
#define DILf    0.05f
#define FULLM   0xffffffffu

// knorm = 315 / (64 * pi * R^9), R = 0.1
#define KNORMf ((float)(315.0 / (64.0 * 3.14159265358979323846 * 1e-9)))

// ---------------- scratch ---------------------------------------------------
__device__ float  g_coef[BB * NN];
__device__ __half g_Wh[KC * CC];            // fp16 weights: [kc][o]
__device__ float  g_dcoefS[BB * NN * CC];   // SORTED rows: [b][slot][c]
__device__ float2 g_sPos[BB * NN + 32];     // sorted positions + sentinel pad
__device__ int    g_slotOf[BB * NN];        // orig j -> slot
__device__ int    g_origOf[BB * NN];        // slot -> orig j
__device__ int    g_cellCnt[BB * NCELL];
__device__ int    g_cellStart[BB * NCELL];

__device__ __forceinline__ int cell_of(float x, float y) {
    int cx = (int)(x * (float)GG); cx = min(GG - 1, max(0, cx));
    int cy = (int)(y * (float)GG); cy = min(GG - 1, max(0, cy));
    return cy * GG + cx;
}

// ---------------- prep1: coef + fp16 weight transpose + sentinel ------------
__global__ void prep1_kernel(const float* __restrict__ locs,
                             const float* __restrict__ density,
                             const float* __restrict__ weight) {
    int idx = blockIdx.x * blockDim.x + threadIdx.x;
    if (idx < BB * NN) {
        float im  = locs[idx * 3 + 2];
        float den = density[idx];
        g_coef[idx] = 1.0f / (im * den);
    }
    if (idx < 32) g_sPos[BB * NN + idx] = make_float2(1e9f, 1e9f);
    if (idx < CC * CC * NK) {
        int o = idx / (CC * NK);
        int r = idx - o * (CC * NK);
        int c = r / NK;
        int k = r - c * NK;
        g_Wh[(k * CC + c) * CC + o] = __float2half_rn(weight[idx]);
    }
}

// ---------------- binning: smem-cached count + scan + ordered scatter -------
__global__ __launch_bounds__(800) void bin_kernel(const float* __restrict__ locs) {
    __shared__ float2 s_pos[NN];
    __shared__ int    s_cell[NN];
    __shared__ int    s_cnt[NCELL];

    int b    = blockIdx.x;
    int tid  = threadIdx.x;
    int w    = tid >> 5;       // warp = cell (warps 0..24)
    int lane = tid & 31;

    // one pass caches positions + cell ids
    for (int t = tid; t < NN; t += 800) {
        const float* lp = locs + (size_t)(b * NN + t) * 3;
        float x = lp[0], y = lp[1];
        s_pos[t]  = make_float2(x, y);
        s_cell[t] = cell_of(x, y);
    }
    __syncthreads();

    if (w < NCELL) {
        int cnt = 0;
        for (int j0 = 0; j0 < NN; j0 += 32)
            cnt += __popc(__ballot_sync(FULLM, s_cell[j0 + lane] == w));
        if (lane == 0) s_cnt[w] = cnt;
    }
    __syncthreads();
    if (w < NCELL) {
        int v = (lane < w) ? s_cnt[lane] : 0;
        #pragma unroll
        for (int o = 16; o; o >>= 1) v += __shfl_xor_sync(FULLM, v, o);
        int off = v;                              // exclusive prefix
        if (lane == 0) {
            g_cellStart[b * NCELL + w] = off;
            g_cellCnt[b * NCELL + w]   = s_cnt[w];
        }
        for (int j0 = 0; j0 < NN; j0 += 32) {
            int j = j0 + lane;
            bool match = (s_cell[j] == w);
            unsigned m = __ballot_sync(FULLM, match);
            int rank = __popc(m & ((1u << lane) - 1u));
            if (match) {
                int slot = off + rank;
                g_slotOf[b * NN + j]    = slot;
                g_origOf[b * NN + slot] = j;
                g_sPos[b * NN + slot]   = s_pos[j];
            }
            off += __popc(m);
        }
    }
}

// ---------------- prep2: transpose data -> SORTED dcoefS --------------------
__global__ __launch_bounds__(256) void prep2_kernel(const float* __restrict__ data) {
    __shared__ float s[32][33];
    int jt = blockIdx.x;      // 0..63
    int ct = blockIdx.y;      // 0..1
    int b  = blockIdx.z;      // 0..1
    int tx = threadIdx.x;     // 0..31
    int ty = threadIdx.y;     // 0..7

    #pragma unroll
    for (int i = 0; i < 4; i++) {
        int c = ct * 32 + ty + 8 * i;
        s[ty + 8 * i][tx] = data[((size_t)(b * CC + c)) * NN + jt * 32 + tx];
    }
    __syncthreads();
    #pragma unroll
    for (int i = 0; i < 4; i++) {
        int j2 = jt * 32 + ty + 8 * i;
        int slot = g_slotOf[b * NN + j2];
        g_dcoefS[((size_t)(b * NN + slot)) * CC + ct * 32 + tx] =
            s[tx][ty + 8 * i] * g_coef[b * NN + j2];
    }
}

// ---------------- main: 2 warps/particle, slim entries + pipelined drain ----
__device__ __forceinline__ float wfun(float t) {
    t = fmaxf(t, 0.0f);
    return (t * t) * (t * KNORMf);
}

#define WBF 640   // floats per warp region (2560B): 33*12=396 entry floats, 576 deposit

__global__ __launch_bounds__(128, 9) void convsp_main_kernel(
        const float* __restrict__ bias, float* __restrict__ out) {
    __shared__ __align__(16) float buf[4][WBF];       // 10.25 KB
    __shared__ __align__(16) float2 part[2][32];      // pair partial results

    int b    = blockIdx.x >> 10;          // 2048 blocks: 1024 per batch
    int tid  = threadIdx.x;
    int warp = tid >> 5;                  // 0..3
    int lane = tid & 31;
    int p    = warp >> 1;                 // particle in block: 0..1
    int half = warp & 1;                  // which warp of the pair

    int i_slot = (blockIdx.x & 1023) * 2 + p;         // SORTED order
    const float2* sp = g_sPos + (size_t)b * NN;

    float2 pi = __ldg(&sp[i_slot]);
    float xi = pi.x, yi = pi.y;

    int cx = min(GG - 1, max(0, (int)(xi * (float)GG)));
    int cy = min(GG - 1, max(0, (int)(yi * (float)GG)));
    int cx0 = max(0, cx - 1), cx1 = min(GG - 1, cx + 1);
    int cy0 = max(0, cy - 1), cy1 = min(GG - 1, cy + 1);

    float a0x = 0.f, a1x = 0.f, a2x = 0.f, a3x = 0.f, a4x = 0.f,
          a5x = 0.f, a6x = 0.f, a7x = 0.f, a8x = 0.f;
    float a0y = 0.f, a1y = 0.f, a2y = 0.f, a3y = 0.f, a4y = 0.f,
          a5y = 0.f, a6y = 0.f, a7y = 0.f, a8y = 0.f;

    const float2* dcF = reinterpret_cast<const float2*>(g_dcoefS)
                        + ((size_t)b * NN * 32) + lane;

    float* wbF = buf[warp];

    for (int yy = cy0; yy <= cy1; yy++) {
        int c0 = b * NCELL + yy * GG + cx0;
        int c1 = b * NCELL + yy * GG + cx1;
        int rs = __ldg(&g_cellStart[c0]);
        int re = __ldg(&g_cellStart[c1]) + __ldg(&g_cellCnt[c1]);

        // pair-split: this warp takes alternating 32-wide tiles
        for (int t = rs + half * 32; t < re; t += 64) {
            // ---- Phase A: lane-parallel w-compute + compaction ----
            int slot = t + lane;
            float2 pj = __ldg(&sp[slot]);     // sentinel pad covers tail
            float dx = xi - pj.x;
            float dy = yi - pj.y;
            if (slot >= re) dx = 1e9f;

            float bxm = dx - DILf, bxp = dx + DILf;
            float bym = dy - DILf, byp = dy + DILf;
            float rx0 = fmaf(-bxm, bxm, R2f);
            float rx1 = fmaf(-dx,  dx,  R2f);
            float rx2 = fmaf(-bxp, bxp, R2f);
            float ay0 = bym * bym;
            float ay1 = dy * dy;
            float ay2 = byp * byp;

            float w0 = wfun(rx0 - ay0);
            float w1 = wfun(rx0 - ay1);
            float w2 = wfun(rx0 - ay2);
            float w3 = wfun(rx1 - ay0);
            float w4 = wfun(rx1 - ay1);
            float w5 = wfun(rx1 - ay2);
            float w6 = wfun(rx2 - ay0);
            float w7 = wfun(rx2 - ay1);
            float w8 = wfun(rx2 - ay2);

            // exact union test: some rx_a - ay_b > 0  <=>  some w > 0
            bool active = fmaxf(rx0, fmaxf(rx1, rx2)) >
                          fminf(ay0, fminf(ay1, ay2));

            unsigned m = __ballot_sync(FULLM, active);
            int cnt = __popc(m);
            if (active) {
                int rank = __popc(m & ((1u << lane) - 1u));
                float* e = wbF + rank * 12;
                *reinterpret_cast<float4*>(e + 0) =
                    make_float4(w0, w1, w2, w3);
                *reinterpret_cast<float4*>(e + 4) =
                    make_float4(w4, w5, w6, w7);
                *reinterpret_cast<float4*>(e + 8) =
                    make_float4(w8, __int_as_float(slot), 0.f, 0.f);
            }
            // sentinel entry at rank cnt (prefetch target, never FMA'd)
            if (lane == 0)
                *reinterpret_cast<float4*>(wbF + cnt * 12 + 8) =
                    make_float4(0.f, __int_as_float(0), 0.f, 0.f);
            __syncwarp();

            // ---- Phase B: entry-serial, software-pipelined dc load ----
            if (cnt > 0) {
                float4 q2 = *reinterpret_cast<const float4*>(wbF + 8);
                float2 dc = __ldg(&dcF[(size_t)__float_as_int(q2.y) << 5]);
                float w8c = q2.x;
                for (int e = 0; e < cnt; e++) {
                    const float* ep = wbF + e * 12;
                    float4 q2n = *reinterpret_cast<const float4*>(ep + 20);
                    float2 dcn = __ldg(
                        &dcF[(size_t)__float_as_int(q2n.y) << 5]);
                    float4 q0 = *reinterpret_cast<const float4*>(ep + 0);
                    float4 q1 = *reinterpret_cast<const float4*>(ep + 4);
                    a0x = fmaf(q0.x, dc.x, a0x); a0y = fmaf(q0.x, dc.y, a0y);
                    a1x = fmaf(q0.y, dc.x, a1x); a1y = fmaf(q0.y, dc.y, a1y);
                    a2x = fmaf(q0.z, dc.x, a2x); a2y = fmaf(q0.z, dc.y, a2y);
                    a3x = fmaf(q0.w, dc.x, a3x); a3y = fmaf(q0.w, dc.y, a3y);
                    a4x = fmaf(q1.x, dc.x, a4x); a4y = fmaf(q1.x, dc.y, a4y);
                    a5x = fmaf(q1.y, dc.x, a5x); a5y = fmaf(q1.y, dc.y, a5y);
                    a6x = fmaf(q1.z, dc.x, a6x); a6y = fmaf(q1.z, dc.y, a6y);
                    a7x = fmaf(q1.w, dc.x, a7x); a7y = fmaf(q1.w, dc.y, a7y);
                    a8x = fmaf(w8c,  dc.x, a8x); a8y = fmaf(w8c,  dc.y, a8y);
                    w8c = q2n.x;
                    dc  = dcn;
                }
            }
            __syncwarp();
        }
    }

    // ---- deposit partial field (576 floats) into this warp's smem buf ----
    __syncwarp();
    {
        float2* wf2 = reinterpret_cast<float2*>(wbF);
        wf2[0 * 32 + lane] = make_float2(a0x, a0y);
        wf2[1 * 32 + lane] = make_float2(a1x, a1y);
        wf2[2 * 32 + lane] = make_float2(a2x, a2y);
        wf2[3 * 32 + lane] = make_float2(a3x, a3y);
        wf2[4 * 32 + lane] = make_float2(a4x, a4y);
        wf2[5 * 32 + lane] = make_float2(a5x, a5y);
        wf2[6 * 32 + lane] = make_float2(a6x, a6y);
        wf2[7 * 32 + lane] = make_float2(a7x, a7y);
        wf2[8 * 32 + lane] = make_float2(a8x, a8y);
    }
    __syncthreads();

    // ---- fused GEMV over this warp's kc half; lane = o-pair (fp16 W) -----
    // g_Wh[kc][o] fp16: lane loads __half2 (o = 2*lane, 2*lane+1);
    // 32 lanes x 4B = 128B = ONE cache line per kc (vs two for fp32).
    const float4*  fqA = reinterpret_cast<const float4*>(buf[2 * p]);
    const float4*  fqB = reinterpret_cast<const float4*>(buf[2 * p + 1]);
    const __half2* wh  = reinterpret_cast<const __half2*>(g_Wh) + lane;
    float p00 = 0.f, p01 = 0.f, p10 = 0.f, p11 = 0.f;
    float p20 = 0.f, p21 = 0.f, p30 = 0.f, p31 = 0.f;

    int q0i = half * (KC / 8);           // 72 quad-iters per warp
    #pragma unroll 4
    for (int q = q0i; q < q0i + KC / 8; q++) {
        float4 fa = fqA[q];
        float4 fb = fqB[q];
        float2 v0 = __half22float2(__ldg(&wh[(q * 4 + 0) * 32]));
        float2 v1 = __half22float2(__ldg(&wh[(q * 4 + 1) * 32]));
        float2 v2 = __half22float2(__ldg(&wh[(q * 4 + 2) * 32]));
        float2 v3 = __half22float2(__ldg(&wh[(q * 4 + 3) * 32]));
        float fx = fa.x + fb.x, fy = fa.y + fb.y;
        float fz = fa.z + fb.z, fw = fa.w + fb.w;
        p00 = fmaf(v0.x, fx, p00); p01 = fmaf(v0.y, fx, p01);
        p10 = fmaf(v1.x, fy, p10); p11 = fmaf(v1.y, fy, p11);
        p20 = fmaf(v2.x, fz, p20); p21 = fmaf(v2.y, fz, p21);
        p30 = fmaf(v3.x, fw, p30); p31 = fmaf(v3.y, fw, p31);
    }
    float r0 = (p00 + p10) + (p20 + p30);
    float r1 = (p01 + p11) + (p21 + p31);

    if (half == 1) part[p][lane] = make_float2(r0, r1);
    __syncthreads();

    if (half == 0) {
        float2 pr = part[p][lane];
        int orig = __ldg(&g_origOf[b * NN + i_slot]);
        float2 bv = *reinterpret_cast<const float2*>(&bias[2 * lane]);
        out[((size_t)b * CC + 2 * lane)     * NN + orig] = bv.x + r0 + pr.x;
        out[((size_t)b * CC + 2 * lane + 1) * NN + orig] = bv.y + r1 + pr.y;
    }
}

// ---------------- launcher --------------------------------------------------
extern "C" void kernel_launch(void* const* d_in, const int* in_sizes, int n_in,
                              void* d_out, int out_size) {
    // Bind inputs by unique element counts:
    // locs 12288, data 262144, density 4096, weight 36864, bias 64.
    const float* locs = nullptr;
    const float* data = nullptr;
    const float* density = nullptr;
    const float* weight = nullptr;
    const float* bias = nullptr;
    for (int idx = 0; idx < n_in; idx++) {
        switch (in_sizes[idx]) {
            case 12288:  locs    = (const float*)d_in[idx]; break;
            case 262144: data    = (const float*)d_in[idx]; break;
            case 4096:   density = (const float*)d_in[idx]; break;
            case 36864:  weight  = (const float*)d_in[idx]; break;
            case 64:     bias    = (const float*)d_in[idx]; break;
            default: break;
        }
    }
    float* out = (float*)d_out;

    prep1_kernel<<<144, 256>>>(locs, density, weight);
    bin_kernel<<<BB, 800>>>(locs);
    prep2_kernel<<<dim3(64, 2, 2), dim3(32, 8)>>>(data);
    convsp_main_kernel<<<2048, 128>>>(bias, out);
}

// round 12
// speedup vs baseline: 3.3919x; 1.0639x over previous
#include <cuda_runtime.h>
#include <cuda_fp16.h>
#include <math.h>

#define BB 2
#define NN 2048
#define CC 64
#define NK 9
#define KC 576            // NK * CC
#define GG 5              // 5x5 bins, cell 0.2 > prune radius 0.171
#define NCELL 25

#define R2f     0.01f
#define DILf    0.05f
#define FULLM   0xffffffffu

// knorm = 315 / (64 * pi * R^9), R = 0.1
#define KNORMf ((float)(315.0 / (64.0 * 3.14159265358979323846 * 1e-9)))

// ---------------- scratch ---------------------------------------------------
__device__ float  g_coef[BB * NN];
// W4: [kc/2][o/2] -> 8B = halves (o0@kc0, o1@kc0, o0@kc1, o1@kc1)
__device__ __half g_W4[(KC / 2) * 32 * 4];
__device__ float  g_dcoefS[BB * NN * CC];   // SORTED rows: [b][slot][c]
__device__ float2 g_sPos[BB * NN + 32];     // sorted positions + sentinel pad
__device__ int    g_slotOf[BB * NN];        // orig j -> slot
__device__ int    g_origOf[BB * NN];        // slot -> orig j
__device__ int    g_cellCnt[BB * NCELL];
__device__ int    g_cellStart[BB * NCELL];

__device__ __forceinline__ int cell_of(float x, float y) {
    int cx = (int)(x * (float)GG); cx = min(GG - 1, max(0, cx));
    int cy = (int)(y * (float)GG); cy = min(GG - 1, max(0, cy));
    return cy * GG + cx;
}

// ---------------- setup: blocks 0-1 bin+coef; blocks 2+ weight pack ---------
__global__ __launch_bounds__(800) void setup_kernel(
        const float* __restrict__ locs,
        const float* __restrict__ density,
        const float* __restrict__ weight) {
    if (blockIdx.x >= BB) {
        // ---- weight conversion + sentinel ----
        int idx = (blockIdx.x - BB) * 800 + threadIdx.x;
        if (idx < CC * CC * NK) {
            int o = idx / (CC * NK);
            int r = idx - o * (CC * NK);
            int c = r / NK;
            int k = r - c * NK;
            int kc = k * CC + c;
            __half* h4 = reinterpret_cast<__half*>(g_W4);
            h4[(((kc >> 1) * 32 + (o >> 1)) << 2) + ((kc & 1) << 1) + (o & 1)]
                = __float2half_rn(weight[idx]);
        } else if (idx < CC * CC * NK + 32) {
            g_sPos[BB * NN + (idx - CC * CC * NK)] = make_float2(1e9f, 1e9f);
        }
        return;
    }

    // ---- binning + coef for batch b ----
    __shared__ float2 s_pos[NN];
    __shared__ int    s_cell[NN];
    __shared__ int    s_cnt[NCELL];

    int b    = blockIdx.x;
    int tid  = threadIdx.x;
    int w    = tid >> 5;       // warp = cell (warps 0..24)
    int lane = tid & 31;

    for (int t = tid; t < NN; t += 800) {
        const float* lp = locs + (size_t)(b * NN + t) * 3;
        float x = lp[0], y = lp[1], im = lp[2];
        s_pos[t]  = make_float2(x, y);
        s_cell[t] = cell_of(x, y);
        g_coef[b * NN + t] = 1.0f / (im * density[b * NN + t]);
    }
    __syncthreads();

    if (w < NCELL) {
        int cnt = 0;
        for (int j0 = 0; j0 < NN; j0 += 32)
            cnt += __popc(__ballot_sync(FULLM, s_cell[j0 + lane] == w));
        if (lane == 0) s_cnt[w] = cnt;
    }
    __syncthreads();
    if (w < NCELL) {
        int v = (lane < w) ? s_cnt[lane] : 0;
        #pragma unroll
        for (int o = 16; o; o >>= 1) v += __shfl_xor_sync(FULLM, v, o);
        int off = v;                              // exclusive prefix
        if (lane == 0) {
            g_cellStart[b * NCELL + w] = off;
            g_cellCnt[b * NCELL + w]   = s_cnt[w];
        }
        for (int j0 = 0; j0 < NN; j0 += 32) {
            int j = j0 + lane;
            bool match = (s_cell[j] == w);
            unsigned m = __ballot_sync(FULLM, match);
            int rank = __popc(m & ((1u << lane) - 1u));
            if (match) {
                int slot = off + rank;
                g_slotOf[b * NN + j]    = slot;
                g_origOf[b * NN + slot] = j;
                g_sPos[b * NN + slot]   = s_pos[j];
            }
            off += __popc(m);
        }
    }
}

// ---------------- prep2: transpose data -> SORTED dcoefS --------------------
__global__ __launch_bounds__(256) void prep2_kernel(const float* __restrict__ data) {
    __shared__ float s[32][33];
    int jt = blockIdx.x;      // 0..63
    int ct = blockIdx.y;      // 0..1
    int b  = blockIdx.z;      // 0..1
    int tx = threadIdx.x;     // 0..31
    int ty = threadIdx.y;     // 0..7

    #pragma unroll
    for (int i = 0; i < 4; i++) {
        int c = ct * 32 + ty + 8 * i;
        s[ty + 8 * i][tx] = data[((size_t)(b * CC + c)) * NN + jt * 32 + tx];
    }
    __syncthreads();
    #pragma unroll
    for (int i = 0; i < 4; i++) {
        int j2 = jt * 32 + ty + 8 * i;
        int slot = g_slotOf[b * NN + j2];
        g_dcoefS[((size_t)(b * NN + slot)) * CC + ct * 32 + tx] =
            s[tx][ty + 8 * i] * g_coef[b * NN + j2];
    }
}

// ---------------- main: 2 warps/particle, slim entries + pipelined drain ----
__device__ __forceinline__ float wfun(float t) {
    t = fmaxf(t, 0.0f);
    return (t * t) * (t * KNORMf);
}

#define WBF 640   // floats per warp region (2560B): 33*12=396 entry floats, 576 deposit

__global__ __launch_bounds__(128, 9) void convsp_main_kernel(
        const float* __restrict__ bias, float* __restrict__ out) {
    __shared__ __align__(16) float buf[4][WBF];       // 10.25 KB
    __shared__ __align__(16) float2 part[2][32];      // pair partial results

    int b    = blockIdx.x >> 10;          // 2048 blocks: 1024 per batch
    int tid  = threadIdx.x;
    int warp = tid >> 5;                  // 0..3
    int lane = tid & 31;
    int p    = warp >> 1;                 // particle in block: 0..1
    int half = warp & 1;                  // which warp of the pair

    int i_slot = (blockIdx.x & 1023) * 2 + p;         // SORTED order
    const float2* sp = g_sPos + (size_t)b * NN;

    float2 pi = __ldg(&sp[i_slot]);
    float xi = pi.x, yi = pi.y;

    int cx = min(GG - 1, max(0, (int)(xi * (float)GG)));
    int cy = min(GG - 1, max(0, (int)(yi * (float)GG)));
    int cx0 = max(0, cx - 1), cx1 = min(GG - 1, cx + 1);
    int cy0 = max(0, cy - 1), cy1 = min(GG - 1, cy + 1);

    float a0x = 0.f, a1x = 0.f, a2x = 0.f, a3x = 0.f, a4x = 0.f,
          a5x = 0.f, a6x = 0.f, a7x = 0.f, a8x = 0.f;
    float a0y = 0.f, a1y = 0.f, a2y = 0.f, a3y = 0.f, a4y = 0.f,
          a5y = 0.f, a6y = 0.f, a7y = 0.f, a8y = 0.f;

    const float2* dcF = reinterpret_cast<const float2*>(g_dcoefS)
                        + ((size_t)b * NN * 32) + lane;

    float* wbF = buf[warp];

    for (int yy = cy0; yy <= cy1; yy++) {
        int c0 = b * NCELL + yy * GG + cx0;
        int c1 = b * NCELL + yy * GG + cx1;
        int rs = __ldg(&g_cellStart[c0]);
        int re = __ldg(&g_cellStart[c1]) + __ldg(&g_cellCnt[c1]);

        // pair-split: this warp takes alternating 32-wide tiles
        for (int t = rs + half * 32; t < re; t += 64) {
            // ---- Phase A: lane-parallel w-compute + compaction ----
            int slot = t + lane;
            float2 pj = __ldg(&sp[slot]);     // sentinel pad covers tail
            float dx = xi - pj.x;
            float dy = yi - pj.y;
            if (slot >= re) dx = 1e9f;

            float bxm = dx - DILf, bxp = dx + DILf;
            float bym = dy - DILf, byp = dy + DILf;
            float rx0 = fmaf(-bxm, bxm, R2f);
            float rx1 = fmaf(-dx,  dx,  R2f);
            float rx2 = fmaf(-bxp, bxp, R2f);
            float ay0 = bym * bym;
            float ay1 = dy * dy;
            float ay2 = byp * byp;

            float w0 = wfun(rx0 - ay0);
            float w1 = wfun(rx0 - ay1);
            float w2 = wfun(rx0 - ay2);
            float w3 = wfun(rx1 - ay0);
            float w4 = wfun(rx1 - ay1);
            float w5 = wfun(rx1 - ay2);
            float w6 = wfun(rx2 - ay0);
            float w7 = wfun(rx2 - ay1);
            float w8 = wfun(rx2 - ay2);

            // exact union test: some rx_a - ay_b > 0  <=>  some w > 0
            bool active = fmaxf(rx0, fmaxf(rx1, rx2)) >
                          fminf(ay0, fminf(ay1, ay2));

            unsigned m = __ballot_sync(FULLM, active);
            int cnt = __popc(m);
            if (active) {
                int rank = __popc(m & ((1u << lane) - 1u));
                float* e = wbF + rank * 12;
                *reinterpret_cast<float4*>(e + 0) =
                    make_float4(w0, w1, w2, w3);
                *reinterpret_cast<float4*>(e + 4) =
                    make_float4(w4, w5, w6, w7);
                *reinterpret_cast<float4*>(e + 8) =
                    make_float4(w8, __int_as_float(slot), 0.f, 0.f);
            }
            // sentinel entry at rank cnt (prefetch target, never FMA'd)
            if (lane == 0)
                *reinterpret_cast<float4*>(wbF + cnt * 12 + 8) =
                    make_float4(0.f, __int_as_float(0), 0.f, 0.f);
            __syncwarp();

            // ---- Phase B: entry-serial, software-pipelined dc load ----
            if (cnt > 0) {
                float4 q2 = *reinterpret_cast<const float4*>(wbF + 8);
                float2 dc = __ldg(&dcF[(size_t)__float_as_int(q2.y) << 5]);
                float w8c = q2.x;
                for (int e = 0; e < cnt; e++) {
                    const float* ep = wbF + e * 12;
                    float4 q2n = *reinterpret_cast<const float4*>(ep + 20);
                    float2 dcn = __ldg(
                        &dcF[(size_t)__float_as_int(q2n.y) << 5]);
                    float4 q0 = *reinterpret_cast<const float4*>(ep + 0);
                    float4 q1 = *reinterpret_cast<const float4*>(ep + 4);
                    a0x = fmaf(q0.x, dc.x, a0x); a0y = fmaf(q0.x, dc.y, a0y);
                    a1x = fmaf(q0.y, dc.x, a1x); a1y = fmaf(q0.y, dc.y, a1y);
                    a2x = fmaf(q0.z, dc.x, a2x); a2y = fmaf(q0.z, dc.y, a2y);
                    a3x = fmaf(q0.w, dc.x, a3x); a3y = fmaf(q0.w, dc.y, a3y);
                    a4x = fmaf(q1.x, dc.x, a4x); a4y = fmaf(q1.x, dc.y, a4y);
                    a5x = fmaf(q1.y, dc.x, a5x); a5y = fmaf(q1.y, dc.y, a5y);
                    a6x = fmaf(q1.z, dc.x, a6x); a6y = fmaf(q1.z, dc.y, a6y);
                    a7x = fmaf(q1.w, dc.x, a7x); a7y = fmaf(q1.w, dc.y, a7y);
                    a8x = fmaf(w8c,  dc.x, a8x); a8y = fmaf(w8c,  dc.y, a8y);
                    w8c = q2n.x;
                    dc  = dcn;
                }
            }
            __syncwarp();
        }
    }

    // ---- deposit partial field (576 floats) into this warp's smem buf ----
    __syncwarp();
    {
        float2* wf2 = reinterpret_cast<float2*>(wbF);
        wf2[0 * 32 + lane] = make_float2(a0x, a0y);
        wf2[1 * 32 + lane] = make_float2(a1x, a1y);
        wf2[2 * 32 + lane] = make_float2(a2x, a2y);
        wf2[3 * 32 + lane] = make_float2(a3x, a3y);
        wf2[4 * 32 + lane] = make_float2(a4x, a4y);
        wf2[5 * 32 + lane] = make_float2(a5x, a5y);
        wf2[6 * 32 + lane] = make_float2(a6x, a6y);
        wf2[7 * 32 + lane] = make_float2(a7x, a7y);
        wf2[8 * 32 + lane] = make_float2(a8x, a8y);
    }
    __syncthreads();

    // ---- merge pair partials into buf[2p] (A: rows 0-3, B: rows 4-8) -----
    {
        float2* A2 = reinterpret_cast<float2*>(buf[2 * p]);
        float2* B2 = reinterpret_cast<float2*>(buf[2 * p + 1]);
        int r0r = half ? 4 : 0;
        int r1r = half ? 9 : 4;
        for (int r = r0r; r < r1r; r++) {
            float2 va = A2[r * 32 + lane];
            float2 vb = B2[r * 32 + lane];
            A2[r * 32 + lane] = make_float2(va.x + vb.x, va.y + vb.y);
        }
    }
    __syncthreads();

    // ---- fused GEMV over this warp's kc half; lane = o-pair (fp16 W4) ----
    // W4[kc2][o2]: one LDG.64 = weights for (2 kc x 2 o); 2 loads per quad.
    const float4* fq = reinterpret_cast<const float4*>(buf[2 * p]);
    const uint2*  w4 = reinterpret_cast<const uint2*>(g_W4) + lane;
    float p00 = 0.f, p01 = 0.f, p10 = 0.f, p11 = 0.f;
    float p20 = 0.f, p21 = 0.f, p30 = 0.f, p31 = 0.f;

    int q0i = half * (KC / 8);           // 72 quad-iters per warp
    #pragma unroll 4
    for (int q = q0i; q < q0i + KC / 8; q++) {
        float4 f4 = fq[q];
        uint2 u0 = __ldg(&w4[(2 * q + 0) * 32]);   // kc 4q, 4q+1
        uint2 u1 = __ldg(&w4[(2 * q + 1) * 32]);   // kc 4q+2, 4q+3
        float2 v0 = __half22float2(*reinterpret_cast<const __half2*>(&u0.x));
        float2 v1 = __half22float2(*reinterpret_cast<const __half2*>(&u0.y));
        float2 v2 = __half22float2(*reinterpret_cast<const __half2*>(&u1.x));
        float2 v3 = __half22float2(*reinterpret_cast<const __half2*>(&u1.y));
        p00 = fmaf(v0.x, f4.x, p00); p01 = fmaf(v0.y, f4.x, p01);
        p10 = fmaf(v1.x, f4.y, p10); p11 = fmaf(v1.y, f4.y, p11);
        p20 = fmaf(v2.x, f4.z, p20); p21 = fmaf(v2.y, f4.z, p21);
        p30 = fmaf(v3.x, f4.w, p30); p31 = fmaf(v3.y, f4.w, p31);
    }
    float r0 = (p00 + p10) + (p20 + p30);
    float r1 = (p01 + p11) + (p21 + p31);

    if (half == 1) part[p][lane] = make_float2(r0, r1);
    __syncthreads();

    if (half == 0) {
        float2 pr = part[p][lane];
        int orig = __ldg(&g_origOf[b * NN + i_slot]);
        float2 bv = *reinterpret_cast<const float2*>(&bias[2 * lane]);
        out[((size_t)b * CC + 2 * lane)     * NN + orig] = bv.x + r0 + pr.x;
        out[((size_t)b * CC + 2 * lane + 1) * NN + orig] = bv.y + r1 + pr.y;
    }
}

// ---------------- launcher --------------------------------------------------
extern "C" void kernel_launch(void* const* d_in, const int* in_sizes, int n_in,
                              void* d_out, int out_size) {
    // Bind inputs by unique element counts:
    // locs 12288, data 262144, density 4096, weight 36864, bias 64.
    const float* locs = nullptr;
    const float* data = nullptr;
    const float* density = nullptr;
    const float* weight = nullptr;
    const float* bias = nullptr;
    for (int idx = 0; idx < n_in; idx++) {
        switch (in_sizes[idx]) {
            case 12288:  locs    = (const float*)d_in[idx]; break;
            case 262144: data    = (const float*)d_in[idx]; break;
            case 4096:   density = (const float*)d_in[idx]; break;
            case 36864:  weight  = (const float*)d_in[idx]; break;
            case 64:     bias    = (const float*)d_in[idx]; break;
            default: break;
        }
    }
    float* out = (float*)d_out;

    // 2 bin blocks + 47 weight blocks (47*800 = 37600 >= 36896)
    setup_kernel<<<BB + 47, 800>>>(locs, density, weight);
    prep2_kernel<<<dim3(64, 2, 2), dim3(32, 8)>>>(data);
    convsp_main_kernel<<<2048, 128>>>(bias, out);
}